// round 9
// baseline (speedup 1.0000x reference)
#include <cuda_runtime.h>

#define NN  100000
#define FIN 128
#define H   24
#define C   16

// Scratch (device globals — no allocation allowed)
__device__ int   g_deg[NN];
__device__ float g_dinv[NN];
__device__ float g_hs1[NN * H];   // dinv[i] * (x[i] @ W1)
__device__ float g_acc1[NN * H];  // sum of incoming hs1 (self added later)
__device__ float g_hs2[NN * C];   // dinv[i] * (relu(layer1) @ W2)
__device__ float g_acc2[NN * C];

// ---------------------------------------------------------------- zero
__global__ void k_zero() {
    int i = blockIdx.x * blockDim.x + threadIdx.x;
    int stride = gridDim.x * blockDim.x;
    for (int j = i; j < NN * H; j += stride) g_acc1[j] = 0.f;
    for (int j = i; j < NN * C; j += stride) g_acc2[j] = 0.f;
    for (int j = i; j < NN;     j += stride) g_deg[j] = 0;
}

// ---------------------------------------------------------------- degree
__global__ void k_deg(const int* __restrict__ dst, int E) {
    int i = blockIdx.x * blockDim.x + threadIdx.x;
    if (i < E) atomicAdd(&g_deg[dst[i]], 1);
}

__global__ void k_dinv() {
    int i = blockIdx.x * blockDim.x + threadIdx.x;
    if (i < NN) g_dinv[i] = rsqrtf((float)g_deg[i] + 1.0f);  // +1 = self loop
}

// ---------------------------------------------------------------- GEMM1: hs1 = dinv * (x @ W1)
// 32 nodes per block, 768 threads = 32 nodes x 24 out-cols.
__global__ void __launch_bounds__(768) k_gemm1(const float* __restrict__ x,
                                               const float* __restrict__ W1) {
    __shared__ float Ws[FIN * H];    // 12 KB
    __shared__ float Xs[32 * FIN];   // 16 KB
    int tid = threadIdx.x;
    for (int i = tid; i < FIN * H; i += 768) Ws[i] = W1[i];
    int base = blockIdx.x * 32;      // NN % 32 == 0
    for (int i = tid; i < 32 * FIN; i += 768) Xs[i] = x[(long long)base * FIN + i];
    __syncthreads();

    int nl = tid / H;                // 0..31
    int f  = tid % H;                // 0..23
    float s = 0.f;
#pragma unroll 8
    for (int k = 0; k < FIN; k++) s += Xs[nl * FIN + k] * Ws[k * H + f];
    int node = base + nl;
    g_hs1[node * H + f] = s * g_dinv[node];
}

// ---------------------------------------------------------------- scatter layer 1 (warp/edge, 24 lanes)
__global__ void k_scat1(const int* __restrict__ dst,
                        const int* __restrict__ src, int E) {
    int g = blockIdx.x * blockDim.x + threadIdx.x;
    int e = g >> 5, lane = g & 31;
    if (e >= E || lane >= H) return;
    int d = dst[e];
    int s = src[e];
    atomicAdd(&g_acc1[d * H + lane], g_hs1[s * H + lane]);
}

// ---------------------------------------------------------------- fused: out1=relu(dinv*(acc1+hs1)+b1); hs2 = dinv*(out1@W2)
__global__ void __launch_bounds__(384) k_gemm2(const float* __restrict__ b1,
                                               const float* __restrict__ W2) {
    __shared__ float W2s[H * C];
    __shared__ float b1s[H];
    __shared__ float rs[16 * H];
    int tid = threadIdx.x;
    if (tid < H * C) W2s[tid] = W2[tid];
    if (tid < H)     b1s[tid] = b1[tid];
    __syncthreads();

    int base = blockIdx.x * 16;      // NN % 16 == 0
    int nl = tid / H, k = tid % H;
    int node = base + nl;
    float a = g_acc1[node * H + k] + g_hs1[node * H + k];   // + self loop
    rs[nl * H + k] = fmaxf(g_dinv[node] * a + b1s[k], 0.f);
    __syncthreads();

    if (tid < 256) {
        int nl2 = tid / C, c = tid % C;
        int node2 = base + nl2;
        float s = 0.f;
#pragma unroll
        for (int kk = 0; kk < H; kk++) s += rs[nl2 * H + kk] * W2s[kk * C + c];
        g_hs2[node2 * C + c] = s * g_dinv[node2];
    }
}

// ---------------------------------------------------------------- scatter layer 2 (half-warp/edge, 16 lanes)
__global__ void k_scat2(const int* __restrict__ dst,
                        const int* __restrict__ src, int E) {
    int g = blockIdx.x * blockDim.x + threadIdx.x;
    int e = g >> 4, lane = g & 15;
    if (e >= E) return;
    int d = dst[e];
    int s = src[e];
    atomicAdd(&g_acc2[d * C + lane], g_hs2[s * C + lane]);
}

// ---------------------------------------------------------------- epilogue: log_softmax(dinv*(acc2+hs2)+b2)
__global__ void k_out(const float* __restrict__ b2, float* __restrict__ out) {
    int g = blockIdx.x * blockDim.x + threadIdx.x;
    int node = g >> 4, c = g & 15;
    if (node >= NN) return;
    float v = g_dinv[node] * (g_acc2[node * C + c] + g_hs2[node * C + c]) + b2[c];
    float m = v;
#pragma unroll
    for (int o = 8; o; o >>= 1) m = fmaxf(m, __shfl_xor_sync(0xffffffffu, m, o, 16));
    float s = expf(v - m);
#pragma unroll
    for (int o = 8; o; o >>= 1) s += __shfl_xor_sync(0xffffffffu, s, o, 16);
    out[node * C + c] = (v - m) - logf(s);
}

// ---------------------------------------------------------------- launch
extern "C" void kernel_launch(void* const* d_in, const int* in_sizes, int n_in,
                              void* d_out, int out_size) {
    const float* x   = (const float*)d_in[0];
    const int*   ei  = (const int*)d_in[1];    // [2, E] — int32 (JAX x64 disabled)
    const float* W1  = (const float*)d_in[2];
    const float* b1  = (const float*)d_in[3];
    const float* W2  = (const float*)d_in[4];
    const float* b2  = (const float*)d_in[5];
    float*       out = (float*)d_out;

    int E = in_sizes[1] / 2;
    const int* dst = ei;        // edge_index[0] = row = target
    const int* src = ei + E;    // edge_index[1] = col = source

    k_zero<<<2048, 256>>>();
    k_deg<<<(E + 255) / 256, 256>>>(dst, E);
    k_dinv<<<(NN + 255) / 256, 256>>>();

    k_gemm1<<<NN / 32, 768>>>(x, W1);

    {
        long long tot = (long long)E * 32;
        k_scat1<<<(int)((tot + 255) / 256), 256>>>(dst, src, E);
    }

    k_gemm2<<<NN / 16, 384>>>(b1, W2);

    {
        long long tot = (long long)E * 16;
        k_scat2<<<(int)((tot + 255) / 256), 256>>>(dst, src, E);
    }

    {
        long long tot = (long long)NN * 16;
        k_out<<<(int)((tot + 255) / 256), 256>>>(b2, out);
    }
}

// round 10
// speedup vs baseline: 2.5194x; 2.5194x over previous
#include <cuda_runtime.h>

#define NN  100000
#define FIN 128
#define H   24
#define C   16

// Scratch (device globals — no allocation allowed), 16B-aligned for float4 ops
__device__ __align__(16) int   g_deg[NN];
__device__ __align__(16) float g_dinv[NN];
__device__ __align__(16) float g_hs1[NN * H];   // dinv[i] * (x[i] @ W1)
__device__ __align__(16) float g_acc1[NN * H];  // sum of incoming hs1
__device__ __align__(16) float g_hs2[NN * C];   // dinv[i] * (relu(layer1) @ W2)
__device__ __align__(16) float g_acc2[NN * C];

__device__ __forceinline__ void red_add_v4(float* p, float4 v) {
    asm volatile("red.global.add.v4.f32 [%0], {%1,%2,%3,%4};"
                 :: "l"(p), "f"(v.x), "f"(v.y), "f"(v.z), "f"(v.w) : "memory");
}

// ---------------------------------------------------------------- zero (float4)
__global__ void k_zero() {
    int i = blockIdx.x * blockDim.x + threadIdx.x;
    int stride = gridDim.x * blockDim.x;
    float4 z = make_float4(0.f, 0.f, 0.f, 0.f);
    float4* a1 = (float4*)g_acc1;
    float4* a2 = (float4*)g_acc2;
    for (int j = i; j < NN * H / 4; j += stride) a1[j] = z;
    for (int j = i; j < NN * C / 4; j += stride) a2[j] = z;
    for (int j = i; j < NN;         j += stride) g_deg[j] = 0;
}

// ---------------------------------------------------------------- degree
__global__ void k_deg(const int* __restrict__ dst, int E) {
    int i = blockIdx.x * blockDim.x + threadIdx.x;
    if (i < E) atomicAdd(&g_deg[dst[i]], 1);
}

__global__ void k_dinv() {
    int i = blockIdx.x * blockDim.x + threadIdx.x;
    if (i < NN) g_dinv[i] = rsqrtf((float)g_deg[i] + 1.0f);  // +1 = self loop
}

// ---------------------------------------------------------------- GEMM1: hs1 = dinv * (x @ W1)
// 32 nodes/block, 192 threads = 32 nodes x 6 thr, 4 features per thread (float4).
// Xs padded to 33 float4/row to avoid bank conflicts across nodes.
__global__ void __launch_bounds__(192) k_gemm1(const float* __restrict__ x,
                                               const float* __restrict__ W1) {
    __shared__ float4 Ws[FIN * 6];      // 128 rows x 24 floats = 12 KB
    __shared__ float4 Xs[32 * 33];      // 32 nodes x 128 floats (padded) ~16.9 KB
    int tid = threadIdx.x;
    const float4* W4 = (const float4*)W1;
    for (int i = tid; i < FIN * 6; i += 192) Ws[i] = W4[i];
    int base = blockIdx.x * 32;         // NN % 32 == 0
    const float4* x4 = (const float4*)(x + (long long)base * FIN);
    for (int i = tid; i < 32 * 32; i += 192) {
        int row = i >> 5, kk = i & 31;
        Xs[row * 33 + kk] = x4[i];
    }
    __syncthreads();

    int nl = tid / 6;                   // node-in-block 0..31
    int ft = tid % 6;                   // float4-feature group 0..5
    float4 acc = make_float4(0.f, 0.f, 0.f, 0.f);
#pragma unroll 4
    for (int kk = 0; kk < 32; kk++) {
        float4 xv = Xs[nl * 33 + kk];
        float xs[4] = {xv.x, xv.y, xv.z, xv.w};
#pragma unroll
        for (int j = 0; j < 4; j++) {
            float4 w = Ws[(kk * 4 + j) * 6 + ft];
            acc.x += xs[j] * w.x;
            acc.y += xs[j] * w.y;
            acc.z += xs[j] * w.z;
            acc.w += xs[j] * w.w;
        }
    }
    int node = base + nl;
    float d = g_dinv[node];
    float4 r = make_float4(acc.x * d, acc.y * d, acc.z * d, acc.w * d);
    ((float4*)g_hs1)[node * 6 + ft] = r;
}

// ---------------------------------------------------------------- scatter layer 1
// 6 work items per edge, each gathers + red.v4 one float4 (24 floats / edge).
__global__ void k_scat1(const int* __restrict__ dst,
                        const int* __restrict__ src, int E) {
    int i = blockIdx.x * blockDim.x + threadIdx.x;
    int e = i / 6;
    if (e >= E) return;
    int j = i - e * 6;
    int d = dst[e];
    int s = src[e];
    float4 v = ((const float4*)g_hs1)[s * 6 + j];
    red_add_v4(&g_acc1[d * H + j * 4], v);
}

// ---------------------------------------------------------------- fused: relu + GEMM2
__global__ void __launch_bounds__(384) k_gemm2(const float* __restrict__ b1,
                                               const float* __restrict__ W2) {
    __shared__ float W2s[H * C];
    __shared__ float b1s[H];
    __shared__ float rs[16 * H];
    int tid = threadIdx.x;
    if (tid < H * C) W2s[tid] = W2[tid];
    if (tid < H)     b1s[tid] = b1[tid];
    __syncthreads();

    int base = blockIdx.x * 16;      // NN % 16 == 0
    int nl = tid / H, k = tid % H;
    int node = base + nl;
    float a = g_acc1[node * H + k] + g_hs1[node * H + k];   // + self loop
    rs[nl * H + k] = fmaxf(g_dinv[node] * a + b1s[k], 0.f);
    __syncthreads();

    if (tid < 256) {
        int nl2 = tid / C, c = tid % C;
        int node2 = base + nl2;
        float s = 0.f;
#pragma unroll
        for (int kk = 0; kk < H; kk++) s += rs[nl2 * H + kk] * W2s[kk * C + c];
        g_hs2[node2 * C + c] = s * g_dinv[node2];
    }
}

// ---------------------------------------------------------------- scatter layer 2
// 4 work items per edge (16 floats / edge).
__global__ void k_scat2(const int* __restrict__ dst,
                        const int* __restrict__ src, int E) {
    int i = blockIdx.x * blockDim.x + threadIdx.x;
    int e = i >> 2;
    if (e >= E) return;
    int j = i & 3;
    int d = dst[e];
    int s = src[e];
    float4 v = ((const float4*)g_hs2)[s * 4 + j];
    red_add_v4(&g_acc2[d * C + j * 4], v);
}

// ---------------------------------------------------------------- epilogue: log_softmax
__global__ void k_out(const float* __restrict__ b2, float* __restrict__ out) {
    int g = blockIdx.x * blockDim.x + threadIdx.x;
    int node = g >> 4, c = g & 15;
    if (node >= NN) return;
    float v = g_dinv[node] * (g_acc2[node * C + c] + g_hs2[node * C + c]) + b2[c];
    float m = v;
#pragma unroll
    for (int o = 8; o; o >>= 1) m = fmaxf(m, __shfl_xor_sync(0xffffffffu, m, o, 16));
    float s = expf(v - m);
#pragma unroll
    for (int o = 8; o; o >>= 1) s += __shfl_xor_sync(0xffffffffu, s, o, 16);
    out[node * C + c] = (v - m) - logf(s);
}

// ---------------------------------------------------------------- launch
extern "C" void kernel_launch(void* const* d_in, const int* in_sizes, int n_in,
                              void* d_out, int out_size) {
    const float* x   = (const float*)d_in[0];
    const int*   ei  = (const int*)d_in[1];    // [2, E] — int32 (JAX x64 disabled)
    const float* W1  = (const float*)d_in[2];
    const float* b1  = (const float*)d_in[3];
    const float* W2  = (const float*)d_in[4];
    const float* b2  = (const float*)d_in[5];
    float*       out = (float*)d_out;

    int E = in_sizes[1] / 2;
    const int* dst = ei;        // edge_index[0] = row = target
    const int* src = ei + E;    // edge_index[1] = col = source

    k_zero<<<1024, 256>>>();
    k_deg<<<(E + 255) / 256, 256>>>(dst, E);
    k_dinv<<<(NN + 255) / 256, 256>>>();

    k_gemm1<<<NN / 32, 192>>>(x, W1);

    {
        long long tot = (long long)E * 6;
        k_scat1<<<(int)((tot + 255) / 256), 256>>>(dst, src, E);
    }

    k_gemm2<<<NN / 16, 384>>>(b1, W2);

    {
        long long tot = (long long)E * 4;
        k_scat2<<<(int)((tot + 255) / 256), 256>>>(dst, src, E);
    }

    {
        long long tot = (long long)NN * 16;
        k_out<<<(int)((tot + 255) / 256), 256>>>(b2, out);
    }
}